// round 15
// baseline (speedup 1.0000x reference)
#include <cuda_runtime.h>
#include <cuda_bf16.h>
#include <math_constants.h>
#include <math.h>
#include <cstdint>

// ---------------------------------------------------------------------------
// Problem constants
// ---------------------------------------------------------------------------
namespace {
constexpr int kD  = 1024;
constexpr int kH  = 8;
constexpr int kFF = 2048;
constexpr int kL  = 3;
constexpr int kB  = 8;
constexpr int kT  = 256;
constexpr int kU  = 1024;
constexpr int kTextV = 128257;
constexpr int kUnitV = 10001;
constexpr float kLnEps = 1e-5f;
constexpr float kTemp  = 0.0005f;
constexpr float kNeg   = -1e9f;
constexpr float kScale = 0.08838834764831845f;  // 1/sqrt(128)
constexpr long long kWipw = (long long)kL * 3 * kD * kD;
constexpr long long kWow  = (long long)kL * kD * kD;
constexpr long long kWf1  = (long long)kL * kFF * kD;
constexpr long long kWf2  = (long long)kL * kD * kFF;
constexpr long long kWEnc = kWipw + kWow + kWf1 + kWf2;
constexpr long long kLipw = 3LL * kD * kD;
constexpr long long kLow  = (long long)kD * kD;
constexpr long long kLf1  = (long long)kFF * kD;
constexpr long long kLf2  = (long long)kD * kFF;
}

// ---------------------------------------------------------------------------
// Scratch (device globals; no allocations allowed).
// ---------------------------------------------------------------------------
__device__ __nv_bfloat16 g_x_u[kB * kU * kD];
__device__ __nv_bfloat16 g_x_t[kB * kT * kD];
__device__ __nv_bfloat16 g_qkv_u[kB * kU * 3 * kD];
__device__ __nv_bfloat16 g_att_u[kB * kU * kD];
__device__ __nv_bfloat16 g_tmp_u[kB * kU * kD];
__device__ __nv_bfloat16 g_ffb_u[kB * kU * kFF];
__device__ __nv_bfloat16 g_qkv_t[kB * kT * 3 * kD];
__device__ __nv_bfloat16 g_att_t[kB * kT * kD];
__device__ __nv_bfloat16 g_tmp_t[kB * kT * kD];
__device__ __nv_bfloat16 g_ffb_t[kB * kT * kFF];
__device__ __nv_bfloat16 g_wbf[2 * kWEnc];
__device__ float g_un[kB * kU];
__device__ float g_tn[kB * kT];
__device__ int   g_pad_u[kB * kU];
__device__ int   g_pad_t[kB * kT];

// ---------------------------------------------------------------------------
// PTX helpers
// ---------------------------------------------------------------------------
__device__ __forceinline__ uint32_t smem_u32(const void* p) {
    return (uint32_t)__cvta_generic_to_shared(p);
}
__device__ __forceinline__ void cp_async16(uint32_t dst, const void* src) {
    asm volatile("cp.async.cg.shared.global [%0], [%1], 16;"
                 :: "r"(dst), "l"(__cvta_generic_to_global(src)));
}
#define CP_COMMIT() asm volatile("cp.async.commit_group;" ::: "memory")
#define CP_WAIT(n)  asm volatile("cp.async.wait_group %0;" :: "n"(n) : "memory")

__device__ __forceinline__ void ldmx4(uint32_t* r, uint32_t a) {
    asm volatile("ldmatrix.sync.aligned.m8n8.x4.shared.b16 {%0,%1,%2,%3}, [%4];"
                 : "=r"(r[0]), "=r"(r[1]), "=r"(r[2]), "=r"(r[3]) : "r"(a));
}
__device__ __forceinline__ void ldmx4t(uint32_t* r, uint32_t a) {
    asm volatile("ldmatrix.sync.aligned.m8n8.x4.trans.shared.b16 {%0,%1,%2,%3}, [%4];"
                 : "=r"(r[0]), "=r"(r[1]), "=r"(r[2]), "=r"(r[3]) : "r"(a));
}
__device__ __forceinline__ void mma_bf16(float* d, const uint32_t* a, const uint32_t* b) {
    asm volatile(
        "mma.sync.aligned.m16n8k16.row.col.f32.bf16.bf16.f32 "
        "{%0,%1,%2,%3}, {%4,%5,%6,%7}, {%8,%9}, {%0,%1,%2,%3};"
        : "+f"(d[0]), "+f"(d[1]), "+f"(d[2]), "+f"(d[3])
        : "r"(a[0]), "r"(a[1]), "r"(a[2]), "r"(a[3]), "r"(b[0]), "r"(b[1]));
}
__device__ __forceinline__ uint32_t packbf(float x, float y) {
    uint32_t r;
    asm("cvt.rn.bf16x2.f32 %0, %1, %2;" : "=r"(r) : "f"(y), "f"(x));
    return r;
}

template <typename OutT>
__device__ __forceinline__ void store2(OutT* p, float x, float y);
template <>
__device__ __forceinline__ void store2<float>(float* p, float x, float y) {
    *(float2*)p = make_float2(x, y);
}
template <>
__device__ __forceinline__ void store2<__nv_bfloat16>(__nv_bfloat16* p, float x, float y) {
    *(__nv_bfloat162*)p = __floats2bfloat162_rn(x, y);
}

// ---------------------------------------------------------------------------
// bf16 tensor-core GEMM (exact R10 version — measured best): C = act(A@B^T+b)
//   CTA 128x128x64, 128 threads (4 warps, 2x2), warp tile 64x64,
//   3-stage cp.async (108KB smem), 2 CTAs/SM.
// ---------------------------------------------------------------------------
template <typename OutT, bool RELU>
__global__ void __launch_bounds__(128, 2)
bf_gemm(const __nv_bfloat16* __restrict__ A, const __nv_bfloat16* __restrict__ B,
        const float* __restrict__ bias, OutT* __restrict__ C,
        int K, int lda, int ldb, int ldc, int innerB,
        long long sAo, long long sAi, long long sBo, long long sBi,
        long long sCo, long long sCi)
{
    constexpr int RS = 144;
    constexpr int STAGE = 256 * RS;
    extern __shared__ char sm[];
    const uint32_t sbase = smem_u32(sm);

    const int z  = blockIdx.z;
    const int zo = z / innerB;
    const int zi = z - zo * innerB;
    A += zo * sAo + zi * sAi;
    B += zo * sBo + zi * sBi;
    C += zo * sCo + zi * sCi;

    const int m0 = blockIdx.y * 128;
    const int n0 = blockIdx.x * 128;
    const int tid = threadIdx.x;
    const int lane = tid & 31;
    const int wid = tid >> 5;
    const int mw = wid >> 1;
    const int nw = wid & 1;

    const __nv_bfloat16* Ag = A + (long long)m0 * lda;
    const __nv_bfloat16* Bg = B + (long long)n0 * ldb;

    auto load_stage = [&](int it) {
        const uint32_t s = sbase + (it % 3) * STAGE;
        const int kof = it * 64;
#pragma unroll
        for (int i = 0; i < 16; i++) {
            const int c = tid + i * 128;
            const int r = c >> 3, cc = c & 7;
            const __nv_bfloat16* src =
                (r < 128) ? Ag + (long long)r * lda + kof + cc * 8
                          : Bg + (long long)(r - 128) * ldb + kof + cc * 8;
            cp_async16(s + r * RS + cc * 16, src);
        }
        CP_COMMIT();
    };

    const int KT = K >> 6;
    load_stage(0);
    if (KT > 1) load_stage(1);

    float acc[4][8][4] = {};

    for (int it = 0; it < KT; it++) {
        if (it + 1 < KT) CP_WAIT(1); else CP_WAIT(0);
        __syncthreads();
        if (it + 2 < KT) load_stage(it + 2);

        const uint32_t s = sbase + (it % 3) * STAGE;
#pragma unroll
        for (int ks = 0; ks < 4; ks++) {
            uint32_t a[4][4], b[4][4];
#pragma unroll
            for (int i = 0; i < 4; i++) {
                const int row = mw * 64 + i * 16 + (lane & 15);
                ldmx4(a[i], s + row * RS + (ks * 2 + (lane >> 4)) * 16);
            }
#pragma unroll
            for (int jj = 0; jj < 4; jj++) {
                const int row = 128 + nw * 64 + jj * 16 + (lane & 7) + ((lane >> 4) << 3);
                ldmx4(b[jj], s + row * RS + (ks * 2 + ((lane >> 3) & 1)) * 16);
            }
#pragma unroll
            for (int i = 0; i < 4; i++)
#pragma unroll
                for (int j = 0; j < 8; j++)
                    mma_bf16(acc[i][j], a[i], &b[j >> 1][(j & 1) * 2]);
        }
    }

    const int r4 = lane >> 2;
    const int c2 = (lane & 3) * 2;
#pragma unroll
    for (int i = 0; i < 4; i++) {
        const int row = m0 + mw * 64 + i * 16 + r4;
#pragma unroll
        for (int j = 0; j < 8; j++) {
            const int col = n0 + nw * 64 + j * 8 + c2;
            float x0 = acc[i][j][0], x1 = acc[i][j][1];
            float x2 = acc[i][j][2], x3 = acc[i][j][3];
            if (bias) {
                const float2 bb = *(const float2*)(bias + col);
                x0 += bb.x; x1 += bb.y; x2 += bb.x; x3 += bb.y;
            }
            if (RELU) {
                x0 = fmaxf(x0, 0.f); x1 = fmaxf(x1, 0.f);
                x2 = fmaxf(x2, 0.f); x3 = fmaxf(x3, 0.f);
            }
            store2(C + (long long)row * ldc + col, x0, x1);
            store2(C + (long long)(row + 8) * ldc + col, x2, x3);
        }
    }
}

// ---------------------------------------------------------------------------
// Fused cross-GEMM + dist + log-softmax:
//   CTA = 128 u-rows x 256 t-cols (full T), K=1024, b = blockIdx.y.
//   256 threads (8 warps, mw=wid>>2 in {0,1}, nw=wid&3 in {0..3}), warp 64x64.
//   After the mainloop the dist transform and the 256-col log-softmax are done
//   in registers + 2KB smem (two-phase max / sum-exp across the 4 col-warps).
// ---------------------------------------------------------------------------
__global__ void __launch_bounds__(256, 1)
cross_dist_kernel(const __nv_bfloat16* __restrict__ xu,
                  const __nv_bfloat16* __restrict__ xt,
                  const float* __restrict__ un, const float* __restrict__ tn,
                  const int* __restrict__ pad_u, const int* __restrict__ pad_t,
                  float* __restrict__ out)
{
    constexpr int RS = 144;
    constexpr int STAGE = 384 * RS;       // A 128 rows + B 256 rows
    extern __shared__ char sm[];
    const uint32_t sbase = smem_u32(sm);
    float* red = (float*)sm;              // reused after mainloop (post-sync)

    const int b  = blockIdx.y;
    const int m0 = blockIdx.x * 128;
    const int tid = threadIdx.x;
    const int lane = tid & 31;
    const int wid = tid >> 5;
    const int mw = wid >> 2;              // 0..1
    const int nw = wid & 3;               // 0..3

    const __nv_bfloat16* Ag = xu + ((long long)b * kU + m0) * kD;
    const __nv_bfloat16* Bg = xt + (long long)b * kT * kD;

    auto load_stage = [&](int it) {
        const uint32_t s = sbase + (it % 3) * STAGE;
        const int kof = it * 64;
#pragma unroll
        for (int i = 0; i < 12; i++) {    // 3072 16B chunks / 256 threads
            const int c = tid + i * 256;
            const int r = c >> 3, cc = c & 7;
            const __nv_bfloat16* src =
                (r < 128) ? Ag + (long long)r * kD + kof + cc * 8
                          : Bg + (long long)(r - 128) * kD + kof + cc * 8;
            cp_async16(s + r * RS + cc * 16, src);
        }
        CP_COMMIT();
    };

    constexpr int KT = kD / 64;           // 16
    load_stage(0);
    load_stage(1);

    float acc[4][8][4] = {};

    for (int it = 0; it < KT; it++) {
        if (it + 1 < KT) CP_WAIT(1); else CP_WAIT(0);
        __syncthreads();
        if (it + 2 < KT) load_stage(it + 2);

        const uint32_t s = sbase + (it % 3) * STAGE;
#pragma unroll
        for (int ks = 0; ks < 4; ks++) {
            uint32_t a[4][4], bfr[4][4];
#pragma unroll
            for (int i = 0; i < 4; i++) {
                const int row = mw * 64 + i * 16 + (lane & 15);
                ldmx4(a[i], s + row * RS + (ks * 2 + (lane >> 4)) * 16);
            }
#pragma unroll
            for (int jj = 0; jj < 4; jj++) {
                const int row = 128 + nw * 64 + jj * 16 + (lane & 7) + ((lane >> 4) << 3);
                ldmx4(bfr[jj], s + row * RS + (ks * 2 + ((lane >> 3) & 1)) * 16);
            }
#pragma unroll
            for (int i = 0; i < 4; i++)
#pragma unroll
                for (int j = 0; j < 8; j++)
                    mma_bf16(acc[i][j], a[i], &bfr[j >> 1][(j & 1) * 2]);
        }
    }
    __syncthreads();                      // all smem reads done; red[] reusable

    const int r4 = lane >> 2;
    const int c2 = (lane & 3) * 2;

    // --- dist transform in registers ---
    float unv[4][2]; int pu[4][2];
#pragma unroll
    for (int i = 0; i < 4; i++) {
        const int row0 = m0 + mw * 64 + i * 16 + r4;
        unv[i][0] = un[b * kU + row0];     pu[i][0] = pad_u[b * kU + row0];
        unv[i][1] = un[b * kU + row0 + 8]; pu[i][1] = pad_u[b * kU + row0 + 8];
    }
    float tnv[8][2]; int pt[8][2];
#pragma unroll
    for (int j = 0; j < 8; j++) {
        const int col = nw * 64 + j * 8 + c2;
        tnv[j][0] = tn[b * kT + col];      pt[j][0] = pad_t[b * kT + col];
        tnv[j][1] = tn[b * kT + col + 1];  pt[j][1] = pad_t[b * kT + col + 1];
    }
#pragma unroll
    for (int i = 0; i < 4; i++)
#pragma unroll
        for (int j = 0; j < 8; j++) {
            acc[i][j][0] = (pu[i][0] | pt[j][0]) ? kNeg
                : -kTemp * (unv[i][0] + tnv[j][0] - 2.f * acc[i][j][0]);
            acc[i][j][1] = (pu[i][0] | pt[j][1]) ? kNeg
                : -kTemp * (unv[i][0] + tnv[j][1] - 2.f * acc[i][j][1]);
            acc[i][j][2] = (pu[i][1] | pt[j][0]) ? kNeg
                : -kTemp * (unv[i][1] + tnv[j][0] - 2.f * acc[i][j][2]);
            acc[i][j][3] = (pu[i][1] | pt[j][1]) ? kNeg
                : -kTemp * (unv[i][1] + tnv[j][1] - 2.f * acc[i][j][3]);
        }

    // --- phase 1: row max over 256 cols (quad shfl + cross-warp smem) ---
    float m[4][2];
#pragma unroll
    for (int i = 0; i < 4; i++) {
        float a0 = -CUDART_INF_F, a1 = -CUDART_INF_F;
#pragma unroll
        for (int j = 0; j < 8; j++) {
            a0 = fmaxf(a0, fmaxf(acc[i][j][0], acc[i][j][1]));
            a1 = fmaxf(a1, fmaxf(acc[i][j][2], acc[i][j][3]));
        }
        a0 = fmaxf(a0, __shfl_xor_sync(0xffffffffu, a0, 1));
        a0 = fmaxf(a0, __shfl_xor_sync(0xffffffffu, a0, 2));
        a1 = fmaxf(a1, __shfl_xor_sync(0xffffffffu, a1, 1));
        a1 = fmaxf(a1, __shfl_xor_sync(0xffffffffu, a1, 2));
        m[i][0] = a0; m[i][1] = a1;
    }
    if ((lane & 3) == 0) {
#pragma unroll
        for (int i = 0; i < 4; i++) {
            const int lr = mw * 64 + i * 16 + r4;
            red[lr * 4 + nw]       = m[i][0];
            red[(lr + 8) * 4 + nw] = m[i][1];
        }
    }
    __syncthreads();
    float rm[4][2];
#pragma unroll
    for (int i = 0; i < 4; i++) {
        const int lr = mw * 64 + i * 16 + r4;
        rm[i][0] = fmaxf(fmaxf(red[lr * 4], red[lr * 4 + 1]),
                         fmaxf(red[lr * 4 + 2], red[lr * 4 + 3]));
        rm[i][1] = fmaxf(fmaxf(red[(lr + 8) * 4], red[(lr + 8) * 4 + 1]),
                         fmaxf(red[(lr + 8) * 4 + 2], red[(lr + 8) * 4 + 3]));
    }
    __syncthreads();

    // --- phase 2: row sum of exp ---
    float sme[4][2];
#pragma unroll
    for (int i = 0; i < 4; i++) {
        float s0 = 0.f, s1 = 0.f;
#pragma unroll
        for (int j = 0; j < 8; j++) {
            s0 += __expf(acc[i][j][0] - rm[i][0]) + __expf(acc[i][j][1] - rm[i][0]);
            s1 += __expf(acc[i][j][2] - rm[i][1]) + __expf(acc[i][j][3] - rm[i][1]);
        }
        s0 += __shfl_xor_sync(0xffffffffu, s0, 1);
        s0 += __shfl_xor_sync(0xffffffffu, s0, 2);
        s1 += __shfl_xor_sync(0xffffffffu, s1, 1);
        s1 += __shfl_xor_sync(0xffffffffu, s1, 2);
        sme[i][0] = s0; sme[i][1] = s1;
    }
    if ((lane & 3) == 0) {
#pragma unroll
        for (int i = 0; i < 4; i++) {
            const int lr = mw * 64 + i * 16 + r4;
            red[lr * 4 + nw]       = sme[i][0];
            red[(lr + 8) * 4 + nw] = sme[i][1];
        }
    }
    __syncthreads();

#pragma unroll
    for (int i = 0; i < 4; i++) {
        const int lr = mw * 64 + i * 16 + r4;
        const float ls0 = __logf(red[lr * 4] + red[lr * 4 + 1]
                               + red[lr * 4 + 2] + red[lr * 4 + 3]);
        const float ls1 = __logf(red[(lr + 8) * 4] + red[(lr + 8) * 4 + 1]
                               + red[(lr + 8) * 4 + 2] + red[(lr + 8) * 4 + 3]);
        const int row0 = m0 + lr;
        float* o0 = out + ((long long)b * kU + row0) * kT;
        float* o1 = o0 + 8LL * kT;
#pragma unroll
        for (int j = 0; j < 8; j++) {
            const int col = nw * 64 + j * 8 + c2;
            store2(o0 + col, acc[i][j][0] - rm[i][0] - ls0,
                             acc[i][j][1] - rm[i][0] - ls0);
            store2(o1 + col, acc[i][j][2] - rm[i][1] - ls1,
                             acc[i][j][3] - rm[i][1] - ls1);
        }
    }
}

// ---------------------------------------------------------------------------
// Fused flash attention (exact R10 version — measured best).
// ---------------------------------------------------------------------------
__global__ void __launch_bounds__(256, 1)
flash_attn(const __nv_bfloat16* __restrict__ qkv, __nv_bfloat16* __restrict__ att,
           const int* __restrict__ pad, int S)
{
    constexpr int RSB = 272;
    constexpr int OFF_Q = 4096;
    constexpr int TILE = 128 * RSB;
    constexpr int OFF_S = OFF_Q + TILE;
    constexpr int STAGE = 2 * TILE;

    extern __shared__ char sm[];
    int* spad = (int*)sm;
    const uint32_t sb = smem_u32(sm);

    const int bh = blockIdx.y;
    const int b = bh >> 3, h = bh & 7;
    const int q0 = blockIdx.x * 128;
    const int tid = threadIdx.x;
    const int lane = tid & 31;
    const int w = tid >> 5;

    for (int i = tid; i < S; i += 256) spad[i] = pad[b * S + i];

    {
        const __nv_bfloat16* qg = qkv + ((long long)b * S + q0) * 3072 + h * 128;
#pragma unroll
        for (int i = 0; i < 8; i++) {
            const int c = tid + i * 256;
            const int r = c >> 4, cc = c & 15;
            cp_async16(sb + OFF_Q + r * RSB + cc * 16, qg + (long long)r * 3072 + cc * 8);
        }
        CP_COMMIT();
    }

    auto load_kv = [&](int t) {
        const uint32_t s = sb + OFF_S + (t & 1) * STAGE;
        const __nv_bfloat16* kg = qkv + ((long long)b * S + t * 128) * 3072 + 1024 + h * 128;
#pragma unroll
        for (int i = 0; i < 16; i++) {
            const int c = tid + i * 256;
            const int r = (c >> 4) & 127, cc = c & 15;
            const int kv = c >> 11;
            cp_async16(s + kv * TILE + r * RSB + cc * 16,
                       kg + (long long)r * 3072 + kv * 1024 + cc * 8);
        }
        CP_COMMIT();
    };

    load_kv(0);
    CP_WAIT(1);
    __syncthreads();

    uint32_t qa[8][4];
#pragma unroll
    for (int kb = 0; kb < 8; kb++) {
        const int row = w * 16 + (lane & 15);
        ldmx4(qa[kb], sb + OFF_Q + row * RSB + (kb * 2 + (lane >> 4)) * 16);
    }

    float o[16][4] = {};
    float m0 = -CUDART_INF_F, m1 = -CUDART_INF_F;
    float l0 = 0.f, l1 = 0.f;
    const int c2 = (lane & 3) * 2;

    const int nt = S >> 7;
    for (int t = 0; t < nt; t++) {
        if (t + 1 < nt) { load_kv(t + 1); CP_WAIT(1); } else { CP_WAIT(0); }
        __syncthreads();
        const uint32_t sK = sb + OFF_S + (t & 1) * STAGE;
        const uint32_t sV = sK + TILE;

        float s[16][4] = {};
#pragma unroll
        for (int kb = 0; kb < 8; kb++) {
#pragma unroll
            for (int jj = 0; jj < 8; jj++) {
                uint32_t kf[4];
                const int row = jj * 16 + (lane & 7) + ((lane >> 4) << 3);
                ldmx4(kf, sK + row * RSB + (kb * 2 + ((lane >> 3) & 1)) * 16);
                mma_bf16(s[jj * 2], qa[kb], &kf[0]);
                mma_bf16(s[jj * 2 + 1], qa[kb], &kf[2]);
            }
        }

        float mt0 = -CUDART_INF_F, mt1 = -CUDART_INF_F;
#pragma unroll
        for (int j = 0; j < 16; j++) {
            const int col = t * 128 + j * 8 + c2;
            const bool p0 = spad[col] != 0, p1 = spad[col + 1] != 0;
            s[j][0] = p0 ? kNeg : s[j][0] * kScale;
            s[j][1] = p1 ? kNeg : s[j][1] * kScale;
            s[j][2] = p0 ? kNeg : s[j][2] * kScale;
            s[j][3] = p1 ? kNeg : s[j][3] * kScale;
            mt0 = fmaxf(mt0, fmaxf(s[j][0], s[j][1]));
            mt1 = fmaxf(mt1, fmaxf(s[j][2], s[j][3]));
        }
        mt0 = fmaxf(mt0, __shfl_xor_sync(0xffffffffu, mt0, 1));
        mt0 = fmaxf(mt0, __shfl_xor_sync(0xffffffffu, mt0, 2));
        mt1 = fmaxf(mt1, __shfl_xor_sync(0xffffffffu, mt1, 1));
        mt1 = fmaxf(mt1, __shfl_xor_sync(0xffffffffu, mt1, 2));

        const float mn0 = fmaxf(m0, mt0), mn1 = fmaxf(m1, mt1);
        const float a0 = __expf(m0 - mn0), a1 = __expf(m1 - mn1);
        m0 = mn0; m1 = mn1;

        float t0 = 0.f, t1 = 0.f;
#pragma unroll
        for (int j = 0; j < 16; j++) {
            s[j][0] = __expf(s[j][0] - mn0);
            s[j][1] = __expf(s[j][1] - mn0);
            s[j][2] = __expf(s[j][2] - mn1);
            s[j][3] = __expf(s[j][3] - mn1);
            t0 += s[j][0] + s[j][1];
            t1 += s[j][2] + s[j][3];
        }
        t0 += __shfl_xor_sync(0xffffffffu, t0, 1);
        t0 += __shfl_xor_sync(0xffffffffu, t0, 2);
        t1 += __shfl_xor_sync(0xffffffffu, t1, 1);
        t1 += __shfl_xor_sync(0xffffffffu, t1, 2);
        l0 = l0 * a0 + t0;
        l1 = l1 * a1 + t1;
#pragma unroll
        for (int j = 0; j < 16; j++) {
            o[j][0] *= a0; o[j][1] *= a0;
            o[j][2] *= a1; o[j][3] *= a1;
        }

#pragma unroll
        for (int kb = 0; kb < 8; kb++) {
            uint32_t pa[4];
            pa[0] = packbf(s[kb * 2][0], s[kb * 2][1]);
            pa[1] = packbf(s[kb * 2][2], s[kb * 2][3]);
            pa[2] = packbf(s[kb * 2 + 1][0], s[kb * 2 + 1][1]);
            pa[3] = packbf(s[kb * 2 + 1][2], s[kb * 2 + 1][3]);
#pragma unroll
            for (int jj = 0; jj < 8; jj++) {
                uint32_t vf[4];
                const int row = kb * 16 + (lane & 7) + (((lane >> 3) & 1) << 3);
                ldmx4t(vf, sV + row * RSB + (jj * 2 + (lane >> 4)) * 16);
                mma_bf16(o[jj * 2], pa, &vf[0]);
                mma_bf16(o[jj * 2 + 1], pa, &vf[2]);
            }
        }
        __syncthreads();
    }

    const float inv0 = 1.f / l0, inv1 = 1.f / l1;
    const int row0 = q0 + w * 16 + (lane >> 2);
    __nv_bfloat16* op0 = att + ((long long)b * S + row0) * 1024 + h * 128;
    __nv_bfloat16* op1 = op0 + 8LL * 1024;
#pragma unroll
    for (int j = 0; j < 16; j++) {
        const int col = j * 8 + c2;
        store2(op0 + col, o[j][0] * inv0, o[j][1] * inv0);
        store2(op1 + col, o[j][2] * inv1, o[j][3] * inv1);
    }
}

// ---------------------------------------------------------------------------
// Fused fp32 -> bf16 convert: 4 arrays in one launch (segment = blockIdx.y).
// ---------------------------------------------------------------------------
struct WConv {
    const float* src[4];
    __nv_bfloat16* dst[4];
    long long n[4];
};
__global__ void f2bf4_kernel(WConv w)
{
    const int seg = blockIdx.y;
    const long long i = ((long long)blockIdx.x * 256 + threadIdx.x) * 4;
    if (i >= w.n[seg]) return;
    const float4 v = *(const float4*)(w.src[seg] + i);
    __nv_bfloat16* o = w.dst[seg] + i;
    *(__nv_bfloat162*)o       = __floats2bfloat162_rn(v.x, v.y);
    *(__nv_bfloat162*)(o + 2) = __floats2bfloat162_rn(v.z, v.w);
}

// ---------------------------------------------------------------------------
// Embedding gather (fp32 table -> bf16) + pad flags
// ---------------------------------------------------------------------------
__global__ void embed_kernel(const int* __restrict__ tok, const float* __restrict__ emb,
                             __nv_bfloat16* __restrict__ x, int* __restrict__ pad, int padidx)
{
    const int n = blockIdx.x;
    const int t = tok[n];
    if (threadIdx.x == 0) pad[n] = (t == padidx) ? 1 : 0;
    const float4* src = (const float4*)(emb + (size_t)t * kD);
    __nv_bfloat162* dst = (__nv_bfloat162*)(x + (size_t)n * kD);
    for (int i = threadIdx.x; i < kD / 4; i += blockDim.x) {
        const float4 v = src[i];
        dst[i * 2]     = __floats2bfloat162_rn(v.x, v.y);
        dst[i * 2 + 1] = __floats2bfloat162_rn(v.z, v.w);
    }
}

// ---------------------------------------------------------------------------
// Reduction helpers (blockDim.x == 256)
// ---------------------------------------------------------------------------
__device__ __forceinline__ float warp_sum(float v) {
#pragma unroll
    for (int o = 16; o > 0; o >>= 1) v += __shfl_xor_sync(0xffffffffu, v, o);
    return v;
}
__device__ __forceinline__ float block_sum(float v, float* sh) {
    v = warp_sum(v);
    if ((threadIdx.x & 31) == 0) sh[threadIdx.x >> 5] = v;
    __syncthreads();
    float r = 0.f;
#pragma unroll
    for (int i = 0; i < 8; i++) r += sh[i];
    __syncthreads();
    return r;
}

// ---------------------------------------------------------------------------
// x = LayerNorm(x + y); optionally also writes |x_out|^2 per row.
// ---------------------------------------------------------------------------
__global__ void add_ln_kernel(__nv_bfloat16* __restrict__ x,
                              const __nv_bfloat16* __restrict__ y,
                              const float* __restrict__ gamma,
                              const float* __restrict__ beta,
                              float* __restrict__ nrm)
{
    __shared__ float sh[8];
    const long long row = blockIdx.x;
    __nv_bfloat16* xp = x + row * kD;
    const __nv_bfloat16* yp = y + row * kD;

    float v[4];
    float s = 0.f;
#pragma unroll
    for (int i = 0; i < 4; i++) {
        const int idx = threadIdx.x + (i << 8);
        v[i] = __bfloat162float(xp[idx]) + __bfloat162float(yp[idx]);
        s += v[i];
    }
    s = block_sum(s, sh);
    const float mean = s * (1.f / kD);
    float sq = 0.f;
#pragma unroll
    for (int i = 0; i < 4; i++) { const float d = v[i] - mean; sq += d * d; }
    sq = block_sum(sq, sh);
    const float r = rsqrtf(sq * (1.f / kD) + kLnEps);
    float nsq = 0.f;
#pragma unroll
    for (int i = 0; i < 4; i++) {
        const int idx = threadIdx.x + (i << 8);
        const __nv_bfloat16 hv = __float2bfloat16_rn((v[i] - mean) * r * gamma[idx] + beta[idx]);
        xp[idx] = hv;
        if (nrm) { const float q = __bfloat162float(hv); nsq += q * q; }
    }
    if (nrm) {
        nsq = block_sum(nsq, sh);
        if (threadIdx.x == 0) nrm[row] = nsq;
    }
}

// ---------------------------------------------------------------------------
// Host orchestration
// ---------------------------------------------------------------------------
namespace {

constexpr size_t kGemmSmem  = 3 * 256 * 144;                              // 110592
constexpr size_t kFlashSmem = 4096 + 128 * 272 + 2 * (2 * 128 * 272);     // 178176
constexpr size_t kCrossSmem = 3 * 384 * 144;                              // 165888

struct EncParams {
    const float *emb, *ipb, *ob, *l1s, *l1b, *f1b, *f2b, *l2s, *l2b;
    const __nv_bfloat16 *ipw, *ow, *f1w, *f2w;
};

void run_encoder(cudaStream_t st, const int* tokens, int Slen, int padidx,
                 const EncParams& P, __nv_bfloat16* x, int* pad,
                 __nv_bfloat16* qkv, __nv_bfloat16* att, __nv_bfloat16* tmp,
                 __nv_bfloat16* ffb, float* norm, cudaEvent_t evWaitL1)
{
    const int Ntok = kB * Slen;
    embed_kernel<<<Ntok, 256, 0, st>>>(tokens, P.emb, x, pad, padidx);

    for (int l = 0; l < kL; l++) {
        if (l == 1 && evWaitL1) cudaStreamWaitEvent(st, evWaitL1, 0);

        const __nv_bfloat16* ipw = P.ipw + (long long)l * 3 * kD * kD;
        const __nv_bfloat16* ow  = P.ow  + (long long)l * kD * kD;
        const __nv_bfloat16* f1w = P.f1w + (long long)l * kFF * kD;
        const __nv_bfloat16* f2w = P.f2w + (long long)l * kD * kFF;
        const float* ipb = P.ipb + (size_t)l * 3 * kD;
        const float* ob  = P.ob  + (size_t)l * kD;
        const float* l1s = P.l1s + (size_t)l * kD;
        const float* l1b = P.l1b + (size_t)l * kD;
        const float* f1b = P.f1b + (size_t)l * kFF;
        const float* f2b = P.f2b + (size_t)l * kD;
        const float* l2s = P.l2s + (size_t)l * kD;
        const float* l2b = P.l2b + (size_t)l * kD;

        bf_gemm<__nv_bfloat16, false><<<dim3(3 * kD / 128, Ntok / 128, 1), 128, kGemmSmem, st>>>(
            x, ipw, ipb, qkv, kD, kD, kD, 3 * kD, 1, 0, 0, 0, 0, 0, 0);

        flash_attn<<<dim3(Slen / 128, kB * kH), 256, kFlashSmem, st>>>(qkv, att, pad, Slen);

        bf_gemm<__nv_bfloat16, false><<<dim3(kD / 128, Ntok / 128, 1), 128, kGemmSmem, st>>>(
            att, ow, ob, tmp, kD, kD, kD, kD, 1, 0, 0, 0, 0, 0, 0);

        add_ln_kernel<<<Ntok, 256, 0, st>>>(x, tmp, l1s, l1b, nullptr);

        bf_gemm<__nv_bfloat16, true><<<dim3(kFF / 128, Ntok / 128, 1), 128, kGemmSmem, st>>>(
            x, f1w, f1b, ffb, kD, kD, kD, kFF, 1, 0, 0, 0, 0, 0, 0);

        bf_gemm<__nv_bfloat16, false><<<dim3(kD / 128, Ntok / 128, 1), 128, kGemmSmem, st>>>(
            ffb, f2w, f2b, tmp, kFF, kFF, kFF, kD, 1, 0, 0, 0, 0, 0, 0);

        add_ln_kernel<<<Ntok, 256, 0, st>>>(x, tmp, l2s, l2b,
                                            l == kL - 1 ? norm : nullptr);
    }
}

}  // namespace

extern "C" void kernel_launch(void* const* d_in, const int* in_sizes, int n_in,
                              void* d_out, int out_size)
{
    (void)in_sizes; (void)n_in; (void)out_size;
    const int* text_tokens = (const int*)d_in[0];
    const int* unit_tokens = (const int*)d_in[1];
    auto f = [&](int i) { return (const float*)d_in[i]; };
    float* out = (float*)d_out;

    cudaFuncSetAttribute(bf_gemm<__nv_bfloat16, false>,
                         cudaFuncAttributeMaxDynamicSharedMemorySize, (int)kGemmSmem);
    cudaFuncSetAttribute(bf_gemm<__nv_bfloat16, true>,
                         cudaFuncAttributeMaxDynamicSharedMemorySize, (int)kGemmSmem);
    cudaFuncSetAttribute(flash_attn,
                         cudaFuncAttributeMaxDynamicSharedMemorySize, (int)kFlashSmem);
    cudaFuncSetAttribute(cross_dist_kernel,
                         cudaFuncAttributeMaxDynamicSharedMemorySize, (int)kCrossSmem);

    __nv_bfloat16 *x_u, *x_t, *qkv_u, *att_u, *tmp_u, *ffb_u;
    __nv_bfloat16 *qkv_t, *att_t, *tmp_t, *ffb_t, *wbf;
    float *un, *tn;
    int *pad_u, *pad_t;
    cudaGetSymbolAddress((void**)&x_u, g_x_u);
    cudaGetSymbolAddress((void**)&x_t, g_x_t);
    cudaGetSymbolAddress((void**)&qkv_u, g_qkv_u);
    cudaGetSymbolAddress((void**)&att_u, g_att_u);
    cudaGetSymbolAddress((void**)&tmp_u, g_tmp_u);
    cudaGetSymbolAddress((void**)&ffb_u, g_ffb_u);
    cudaGetSymbolAddress((void**)&qkv_t, g_qkv_t);
    cudaGetSymbolAddress((void**)&att_t, g_att_t);
    cudaGetSymbolAddress((void**)&tmp_t, g_tmp_t);
    cudaGetSymbolAddress((void**)&ffb_t, g_ffb_t);
    cudaGetSymbolAddress((void**)&wbf, g_wbf);
    cudaGetSymbolAddress((void**)&un, g_un);
    cudaGetSymbolAddress((void**)&tn, g_tn);
    cudaGetSymbolAddress((void**)&pad_u, g_pad_u);
    cudaGetSymbolAddress((void**)&pad_t, g_pad_t);

    EncParams tP, uP;
    {
        const __nv_bfloat16* w = wbf;
        tP = EncParams{f(2), f(4), f(6), f(7), f(8), f(10), f(12), f(13), f(14),
                       w, w + kWipw, w + kWipw + kWow, w + kWipw + kWow + kWf1};
        const __nv_bfloat16* w2 = wbf + kWEnc;
        uP = EncParams{f(15), f(17), f(19), f(20), f(21), f(23), f(25), f(26), f(27),
                       w2, w2 + kWipw, w2 + kWipw + kWow, w2 + kWipw + kWow + kWf1};
    }

    // --- fork ONE side stream (proven compliant footprint) ---
    cudaStream_t s1;
    cudaStreamCreateWithFlags(&s1, cudaStreamNonBlocking);
    cudaEvent_t eFork, eJoin, eConv;
    cudaEventCreateWithFlags(&eFork, cudaEventDisableTiming);
    cudaEventCreateWithFlags(&eJoin, cudaEventDisableTiming);
    cudaEventCreateWithFlags(&eConv, cudaEventDisableTiming);

    cudaEventRecord(eFork, 0);
    cudaStreamWaitEvent(s1, eFork, 0);

    // s1: unit layers 1..2 conversion first, then the full text pipeline.
    {
        __nv_bfloat16* w = wbf + kWEnc;
        WConv b;
        b.src[0] = f(16) + kLipw; b.dst[0] = w + kLipw;                       b.n[0] = 2 * kLipw;
        b.src[1] = f(18) + kLow;  b.dst[1] = w + kWipw + kLow;                b.n[1] = 2 * kLow;
        b.src[2] = f(22) + kLf1;  b.dst[2] = w + kWipw + kWow + kLf1;         b.n[2] = 2 * kLf1;
        b.src[3] = f(24) + kLf2;  b.dst[3] = w + kWipw + kWow + kWf1 + kLf2;  b.n[3] = 2 * kLf2;
        f2bf4_kernel<<<dim3((int)(2 * kLipw / 1024), 4), 256, 0, s1>>>(b);
        cudaEventRecord(eConv, s1);
    }
    {
        WConv wc;
        __nv_bfloat16* w = wbf;
        wc.src[0] = f(3);  wc.dst[0] = w;                       wc.n[0] = kWipw;
        wc.src[1] = f(5);  wc.dst[1] = w + kWipw;               wc.n[1] = kWow;
        wc.src[2] = f(9);  wc.dst[2] = w + kWipw + kWow;        wc.n[2] = kWf1;
        wc.src[3] = f(11); wc.dst[3] = w + kWipw + kWow + kWf1; wc.n[3] = kWf2;
        f2bf4_kernel<<<dim3((int)(kWipw / 1024), 4), 256, 0, s1>>>(wc);
    }
    run_encoder(s1, text_tokens, kT, kTextV - 1, tP, x_t, pad_t,
                qkv_t, att_t, tmp_t, ffb_t, tn, nullptr);
    cudaEventRecord(eJoin, s1);

    // Main stream: unit layer-0 conversion, then unit encoder.
    {
        __nv_bfloat16* w = wbf + kWEnc;
        WConv a;
        a.src[0] = f(16); a.dst[0] = w;                       a.n[0] = kLipw;
        a.src[1] = f(18); a.dst[1] = w + kWipw;               a.n[1] = kLow;
        a.src[2] = f(22); a.dst[2] = w + kWipw + kWow;        a.n[2] = kLf1;
        a.src[3] = f(24); a.dst[3] = w + kWipw + kWow + kWf1; a.n[3] = kLf2;
        f2bf4_kernel<<<dim3((int)(kLipw / 1024), 4), 256>>>(a);
    }
    run_encoder(0, unit_tokens, kU, kUnitV - 1, uP, x_u, pad_u,
                qkv_u, att_u, tmp_u, ffb_u, un, eConv);

    // join, then fused cross + dist + log-softmax
    cudaStreamWaitEvent(0, eJoin, 0);
    cross_dist_kernel<<<dim3(kU / 128, kB), 256, kCrossSmem>>>(
        x_u, x_t, un, tn, pad_u, pad_t, out);
}

// round 16
// speedup vs baseline: 1.0745x; 1.0745x over previous
#include <cuda_runtime.h>
#include <cuda_bf16.h>
#include <math_constants.h>
#include <math.h>
#include <cstdint>

// ---------------------------------------------------------------------------
// Problem constants
// ---------------------------------------------------------------------------
namespace {
constexpr int kD  = 1024;
constexpr int kH  = 8;
constexpr int kFF = 2048;
constexpr int kL  = 3;
constexpr int kB  = 8;
constexpr int kT  = 256;
constexpr int kU  = 1024;
constexpr int kTextV = 128257;
constexpr int kUnitV = 10001;
constexpr float kLnEps = 1e-5f;
constexpr float kTemp  = 0.0005f;
constexpr float kNeg   = -1e9f;
constexpr float kScale = 0.08838834764831845f;  // 1/sqrt(128)
constexpr float kWScale = 16.0f;                // fp8 weight pre-scale
constexpr float kWInv   = 1.0f / 16.0f;
constexpr long long kWipw = (long long)kL * 3 * kD * kD;
constexpr long long kWow  = (long long)kL * kD * kD;
constexpr long long kWf1  = (long long)kL * kFF * kD;
constexpr long long kWf2  = (long long)kL * kD * kFF;
constexpr long long kWEnc = kWipw + kWow;       // bf16 part per encoder
constexpr long long kW8Enc = kWf1 + kWf2;       // fp8 part per encoder
}

// ---------------------------------------------------------------------------
// Scratch (device globals; no allocations allowed).
// ---------------------------------------------------------------------------
__device__ __nv_bfloat16 g_x_u[kB * kU * kD];
__device__ __nv_bfloat16 g_x_t[kB * kT * kD];
__device__ uint8_t       g_x8_u[kB * kU * kD];
__device__ uint8_t       g_x8_t[kB * kT * kD];
__device__ __nv_bfloat16 g_qkv_u[kB * kU * 3 * kD];
__device__ __nv_bfloat16 g_att_u[kB * kU * kD];
__device__ __nv_bfloat16 g_tmp_u[kB * kU * kD];
__device__ uint8_t       g_f8b_u[kB * kU * kFF];
__device__ __nv_bfloat16 g_qkv_t[kB * kT * 3 * kD];
__device__ __nv_bfloat16 g_att_t[kB * kT * kD];
__device__ __nv_bfloat16 g_tmp_t[kB * kT * kD];
__device__ uint8_t       g_f8b_t[kB * kT * kFF];
__device__ __nv_bfloat16 g_wbf[2 * kWEnc];      // ipw | ow per encoder
__device__ uint8_t       g_w8[2 * kW8Enc];      // f1w | f2w per encoder (x16)
__device__ float g_un[kB * kU];
__device__ float g_tn[kB * kT];
__device__ int   g_pad_u[kB * kU];
__device__ int   g_pad_t[kB * kT];

// ---------------------------------------------------------------------------
// PTX helpers
// ---------------------------------------------------------------------------
__device__ __forceinline__ uint32_t smem_u32(const void* p) {
    return (uint32_t)__cvta_generic_to_shared(p);
}
__device__ __forceinline__ void cp_async16(uint32_t dst, const void* src) {
    asm volatile("cp.async.cg.shared.global [%0], [%1], 16;"
                 :: "r"(dst), "l"(__cvta_generic_to_global(src)));
}
#define CP_COMMIT() asm volatile("cp.async.commit_group;" ::: "memory")
#define CP_WAIT(n)  asm volatile("cp.async.wait_group %0;" :: "n"(n) : "memory")

__device__ __forceinline__ void ldmx4(uint32_t* r, uint32_t a) {
    asm volatile("ldmatrix.sync.aligned.m8n8.x4.shared.b16 {%0,%1,%2,%3}, [%4];"
                 : "=r"(r[0]), "=r"(r[1]), "=r"(r[2]), "=r"(r[3]) : "r"(a));
}
__device__ __forceinline__ void ldmx4t(uint32_t* r, uint32_t a) {
    asm volatile("ldmatrix.sync.aligned.m8n8.x4.trans.shared.b16 {%0,%1,%2,%3}, [%4];"
                 : "=r"(r[0]), "=r"(r[1]), "=r"(r[2]), "=r"(r[3]) : "r"(a));
}
__device__ __forceinline__ void mma_bf16(float* d, const uint32_t* a, const uint32_t* b) {
    asm volatile(
        "mma.sync.aligned.m16n8k16.row.col.f32.bf16.bf16.f32 "
        "{%0,%1,%2,%3}, {%4,%5,%6,%7}, {%8,%9}, {%0,%1,%2,%3};"
        : "+f"(d[0]), "+f"(d[1]), "+f"(d[2]), "+f"(d[3])
        : "r"(a[0]), "r"(a[1]), "r"(a[2]), "r"(a[3]), "r"(b[0]), "r"(b[1]));
}
__device__ __forceinline__ void mma_fp8(float* d, const uint32_t* a, const uint32_t* b) {
    asm volatile(
        "mma.sync.aligned.m16n8k32.row.col.f32.e4m3.e4m3.f32 "
        "{%0,%1,%2,%3}, {%4,%5,%6,%7}, {%8,%9}, {%0,%1,%2,%3};"
        : "+f"(d[0]), "+f"(d[1]), "+f"(d[2]), "+f"(d[3])
        : "r"(a[0]), "r"(a[1]), "r"(a[2]), "r"(a[3]), "r"(b[0]), "r"(b[1]));
}
__device__ __forceinline__ uint32_t packbf(float x, float y) {
    uint32_t r;
    asm("cvt.rn.bf16x2.f32 %0, %1, %2;" : "=r"(r) : "f"(y), "f"(x));
    return r;
}
__device__ __forceinline__ uint16_t packf8(float x, float y) {  // low=x, high=y
    uint16_t r;
    asm("cvt.rn.satfinite.e4m3x2.f32 %0, %1, %2;" : "=h"(r) : "f"(y), "f"(x));
    return r;
}

__device__ __forceinline__ void store_pair(float* p, float x, float y) {
    *(float2*)p = make_float2(x, y);
}
__device__ __forceinline__ void store_pair(__nv_bfloat16* p, float x, float y) {
    *(__nv_bfloat162*)p = __floats2bfloat162_rn(x, y);
}
__device__ __forceinline__ void store_pair(uint8_t* p, float x, float y) {
    *(uint16_t*)p = packf8(x, y);
}

// ---------------------------------------------------------------------------
// bf16 tensor-core GEMM (exact R10 version — measured best): C = act(A@B^T+b)
//   CTA 128x128x64, 128 threads (4 warps, 2x2), warp tile 64x64,
//   3-stage cp.async (108KB smem), 2 CTAs/SM.
// ---------------------------------------------------------------------------
template <typename OutT, bool RELU>
__global__ void __launch_bounds__(128, 2)
bf_gemm(const __nv_bfloat16* __restrict__ A, const __nv_bfloat16* __restrict__ B,
        const float* __restrict__ bias, OutT* __restrict__ C,
        int K, int lda, int ldb, int ldc, int innerB,
        long long sAo, long long sAi, long long sBo, long long sBi,
        long long sCo, long long sCi)
{
    constexpr int RS = 144;
    constexpr int STAGE = 256 * RS;
    extern __shared__ char sm[];
    const uint32_t sbase = smem_u32(sm);

    const int z  = blockIdx.z;
    const int zo = z / innerB;
    const int zi = z - zo * innerB;
    A += zo * sAo + zi * sAi;
    B += zo * sBo + zi * sBi;
    C += zo * sCo + zi * sCi;

    const int m0 = blockIdx.y * 128;
    const int n0 = blockIdx.x * 128;
    const int tid = threadIdx.x;
    const int lane = tid & 31;
    const int wid = tid >> 5;
    const int mw = wid >> 1;
    const int nw = wid & 1;

    const __nv_bfloat16* Ag = A + (long long)m0 * lda;
    const __nv_bfloat16* Bg = B + (long long)n0 * ldb;

    auto load_stage = [&](int it) {
        const uint32_t s = sbase + (it % 3) * STAGE;
        const int kof = it * 64;
#pragma unroll
        for (int i = 0; i < 16; i++) {
            const int c = tid + i * 128;
            const int r = c >> 3, cc = c & 7;
            const __nv_bfloat16* src =
                (r < 128) ? Ag + (long long)r * lda + kof + cc * 8
                          : Bg + (long long)(r - 128) * ldb + kof + cc * 8;
            cp_async16(s + r * RS + cc * 16, src);
        }
        CP_COMMIT();
    };

    const int KT = K >> 6;
    load_stage(0);
    if (KT > 1) load_stage(1);

    float acc[4][8][4] = {};

    for (int it = 0; it < KT; it++) {
        if (it + 1 < KT) CP_WAIT(1); else CP_WAIT(0);
        __syncthreads();
        if (it + 2 < KT) load_stage(it + 2);

        const uint32_t s = sbase + (it % 3) * STAGE;
#pragma unroll
        for (int ks = 0; ks < 4; ks++) {
            uint32_t a[4][4], b[4][4];
#pragma unroll
            for (int i = 0; i < 4; i++) {
                const int row = mw * 64 + i * 16 + (lane & 15);
                ldmx4(a[i], s + row * RS + (ks * 2 + (lane >> 4)) * 16);
            }
#pragma unroll
            for (int jj = 0; jj < 4; jj++) {
                const int row = 128 + nw * 64 + jj * 16 + (lane & 7) + ((lane >> 4) << 3);
                ldmx4(b[jj], s + row * RS + (ks * 2 + ((lane >> 3) & 1)) * 16);
            }
#pragma unroll
            for (int i = 0; i < 4; i++)
#pragma unroll
                for (int j = 0; j < 8; j++)
                    mma_bf16(acc[i][j], a[i], &b[j >> 1][(j & 1) * 2]);
        }
    }

    const int r4 = lane >> 2;
    const int c2 = (lane & 3) * 2;
#pragma unroll
    for (int i = 0; i < 4; i++) {
        const int row = m0 + mw * 64 + i * 16 + r4;
#pragma unroll
        for (int j = 0; j < 8; j++) {
            const int col = n0 + nw * 64 + j * 8 + c2;
            float x0 = acc[i][j][0], x1 = acc[i][j][1];
            float x2 = acc[i][j][2], x3 = acc[i][j][3];
            if (bias) {
                const float2 bb = *(const float2*)(bias + col);
                x0 += bb.x; x1 += bb.y; x2 += bb.x; x3 += bb.y;
            }
            if (RELU) {
                x0 = fmaxf(x0, 0.f); x1 = fmaxf(x1, 0.f);
                x2 = fmaxf(x2, 0.f); x3 = fmaxf(x3, 0.f);
            }
            store_pair(C + (long long)row * ldc + col, x0, x1);
            store_pair(C + (long long)(row + 8) * ldc + col, x2, x3);
        }
    }
}

// ---------------------------------------------------------------------------
// fp8 (e4m3) tensor-core GEMM: C = act((A @ B^T) * oscale + bias)
//   Same structure as bf_gemm: CTA 128x128, BK=128 fp8 (same 144B rows),
//   mma.m16n8k32 — fragment byte layout coincides with the bf16 ldmatrix
//   pattern, so addressing is identical. KT = K/128.
// REQUIRES: M%128==0, N%128==0, K%128==0.
// ---------------------------------------------------------------------------
template <typename OutT, bool RELU>
__global__ void __launch_bounds__(128, 2)
f8_gemm(const uint8_t* __restrict__ A, const uint8_t* __restrict__ B,
        const float* __restrict__ bias, OutT* __restrict__ C,
        int K, int lda, int ldb, int ldc, float oscale)
{
    constexpr int RS = 144;
    constexpr int STAGE = 256 * RS;
    extern __shared__ char sm[];
    const uint32_t sbase = smem_u32(sm);

    const int m0 = blockIdx.y * 128;
    const int n0 = blockIdx.x * 128;
    const int tid = threadIdx.x;
    const int lane = tid & 31;
    const int wid = tid >> 5;
    const int mw = wid >> 1;
    const int nw = wid & 1;

    const uint8_t* Ag = A + (long long)m0 * lda;
    const uint8_t* Bg = B + (long long)n0 * ldb;

    auto load_stage = [&](int it) {
        const uint32_t s = sbase + (it % 3) * STAGE;
        const int kof = it * 128;
#pragma unroll
        for (int i = 0; i < 16; i++) {
            const int c = tid + i * 128;
            const int r = c >> 3, cc = c & 7;
            const uint8_t* src =
                (r < 128) ? Ag + (long long)r * lda + kof + cc * 16
                          : Bg + (long long)(r - 128) * ldb + kof + cc * 16;
            cp_async16(s + r * RS + cc * 16, src);
        }
        CP_COMMIT();
    };

    const int KT = K >> 7;
    load_stage(0);
    if (KT > 1) load_stage(1);

    float acc[4][8][4] = {};

    for (int it = 0; it < KT; it++) {
        if (it + 1 < KT) CP_WAIT(1); else CP_WAIT(0);
        __syncthreads();
        if (it + 2 < KT) load_stage(it + 2);

        const uint32_t s = sbase + (it % 3) * STAGE;
#pragma unroll
        for (int ks = 0; ks < 4; ks++) {
            uint32_t a[4][4], b[4][4];
#pragma unroll
            for (int i = 0; i < 4; i++) {
                const int row = mw * 64 + i * 16 + (lane & 15);
                ldmx4(a[i], s + row * RS + (ks * 2 + (lane >> 4)) * 16);
            }
#pragma unroll
            for (int jj = 0; jj < 4; jj++) {
                const int row = 128 + nw * 64 + jj * 16 + (lane & 7) + ((lane >> 4) << 3);
                ldmx4(b[jj], s + row * RS + (ks * 2 + ((lane >> 3) & 1)) * 16);
            }
#pragma unroll
            for (int i = 0; i < 4; i++)
#pragma unroll
                for (int j = 0; j < 8; j++)
                    mma_fp8(acc[i][j], a[i], &b[j >> 1][(j & 1) * 2]);
        }
    }

    const int r4 = lane >> 2;
    const int c2 = (lane & 3) * 2;
#pragma unroll
    for (int i = 0; i < 4; i++) {
        const int row = m0 + mw * 64 + i * 16 + r4;
#pragma unroll
        for (int j = 0; j < 8; j++) {
            const int col = n0 + nw * 64 + j * 8 + c2;
            float x0 = acc[i][j][0] * oscale, x1 = acc[i][j][1] * oscale;
            float x2 = acc[i][j][2] * oscale, x3 = acc[i][j][3] * oscale;
            if (bias) {
                const float2 bb = *(const float2*)(bias + col);
                x0 += bb.x; x1 += bb.y; x2 += bb.x; x3 += bb.y;
            }
            if (RELU) {
                x0 = fmaxf(x0, 0.f); x1 = fmaxf(x1, 0.f);
                x2 = fmaxf(x2, 0.f); x3 = fmaxf(x3, 0.f);
            }
            store_pair(C + (long long)row * ldc + col, x0, x1);
            store_pair(C + (long long)(row + 8) * ldc + col, x2, x3);
        }
    }
}

// ---------------------------------------------------------------------------
// Fused cross-GEMM + dist + log-softmax (R15 version — passed, fewer launches)
// ---------------------------------------------------------------------------
__global__ void __launch_bounds__(256, 1)
cross_dist_kernel(const __nv_bfloat16* __restrict__ xu,
                  const __nv_bfloat16* __restrict__ xt,
                  const float* __restrict__ un, const float* __restrict__ tn,
                  const int* __restrict__ pad_u, const int* __restrict__ pad_t,
                  float* __restrict__ out)
{
    constexpr int RS = 144;
    constexpr int STAGE = 384 * RS;
    extern __shared__ char sm[];
    const uint32_t sbase = smem_u32(sm);
    float* red = (float*)sm;

    const int b  = blockIdx.y;
    const int m0 = blockIdx.x * 128;
    const int tid = threadIdx.x;
    const int lane = tid & 31;
    const int wid = tid >> 5;
    const int mw = wid >> 2;
    const int nw = wid & 3;

    const __nv_bfloat16* Ag = xu + ((long long)b * kU + m0) * kD;
    const __nv_bfloat16* Bg = xt + (long long)b * kT * kD;

    auto load_stage = [&](int it) {
        const uint32_t s = sbase + (it % 3) * STAGE;
        const int kof = it * 64;
#pragma unroll
        for (int i = 0; i < 12; i++) {
            const int c = tid + i * 256;
            const int r = c >> 3, cc = c & 7;
            const __nv_bfloat16* src =
                (r < 128) ? Ag + (long long)r * kD + kof + cc * 8
                          : Bg + (long long)(r - 128) * kD + kof + cc * 8;
            cp_async16(s + r * RS + cc * 16, src);
        }
        CP_COMMIT();
    };

    constexpr int KT = kD / 64;
    load_stage(0);
    load_stage(1);

    float acc[4][8][4] = {};

    for (int it = 0; it < KT; it++) {
        if (it + 1 < KT) CP_WAIT(1); else CP_WAIT(0);
        __syncthreads();
        if (it + 2 < KT) load_stage(it + 2);

        const uint32_t s = sbase + (it % 3) * STAGE;
#pragma unroll
        for (int ks = 0; ks < 4; ks++) {
            uint32_t a[4][4], bfr[4][4];
#pragma unroll
            for (int i = 0; i < 4; i++) {
                const int row = mw * 64 + i * 16 + (lane & 15);
                ldmx4(a[i], s + row * RS + (ks * 2 + (lane >> 4)) * 16);
            }
#pragma unroll
            for (int jj = 0; jj < 4; jj++) {
                const int row = 128 + nw * 64 + jj * 16 + (lane & 7) + ((lane >> 4) << 3);
                ldmx4(bfr[jj], s + row * RS + (ks * 2 + ((lane >> 3) & 1)) * 16);
            }
#pragma unroll
            for (int i = 0; i < 4; i++)
#pragma unroll
                for (int j = 0; j < 8; j++)
                    mma_bf16(acc[i][j], a[i], &bfr[j >> 1][(j & 1) * 2]);
        }
    }
    __syncthreads();

    const int r4 = lane >> 2;
    const int c2 = (lane & 3) * 2;

    float unv[4][2]; int pu[4][2];
#pragma unroll
    for (int i = 0; i < 4; i++) {
        const int row0 = m0 + mw * 64 + i * 16 + r4;
        unv[i][0] = un[b * kU + row0];     pu[i][0] = pad_u[b * kU + row0];
        unv[i][1] = un[b * kU + row0 + 8]; pu[i][1] = pad_u[b * kU + row0 + 8];
    }
    float tnv[8][2]; int pt[8][2];
#pragma unroll
    for (int j = 0; j < 8; j++) {
        const int col = nw * 64 + j * 8 + c2;
        tnv[j][0] = tn[b * kT + col];      pt[j][0] = pad_t[b * kT + col];
        tnv[j][1] = tn[b * kT + col + 1];  pt[j][1] = pad_t[b * kT + col + 1];
    }
#pragma unroll
    for (int i = 0; i < 4; i++)
#pragma unroll
        for (int j = 0; j < 8; j++) {
            acc[i][j][0] = (pu[i][0] | pt[j][0]) ? kNeg
                : -kTemp * (unv[i][0] + tnv[j][0] - 2.f * acc[i][j][0]);
            acc[i][j][1] = (pu[i][0] | pt[j][1]) ? kNeg
                : -kTemp * (unv[i][0] + tnv[j][1] - 2.f * acc[i][j][1]);
            acc[i][j][2] = (pu[i][1] | pt[j][0]) ? kNeg
                : -kTemp * (unv[i][1] + tnv[j][0] - 2.f * acc[i][j][2]);
            acc[i][j][3] = (pu[i][1] | pt[j][1]) ? kNeg
                : -kTemp * (unv[i][1] + tnv[j][1] - 2.f * acc[i][j][3]);
        }

    float m[4][2];
#pragma unroll
    for (int i = 0; i < 4; i++) {
        float a0 = -CUDART_INF_F, a1 = -CUDART_INF_F;
#pragma unroll
        for (int j = 0; j < 8; j++) {
            a0 = fmaxf(a0, fmaxf(acc[i][j][0], acc[i][j][1]));
            a1 = fmaxf(a1, fmaxf(acc[i][j][2], acc[i][j][3]));
        }
        a0 = fmaxf(a0, __shfl_xor_sync(0xffffffffu, a0, 1));
        a0 = fmaxf(a0, __shfl_xor_sync(0xffffffffu, a0, 2));
        a1 = fmaxf(a1, __shfl_xor_sync(0xffffffffu, a1, 1));
        a1 = fmaxf(a1, __shfl_xor_sync(0xffffffffu, a1, 2));
        m[i][0] = a0; m[i][1] = a1;
    }
    if ((lane & 3) == 0) {
#pragma unroll
        for (int i = 0; i < 4; i++) {
            const int lr = mw * 64 + i * 16 + r4;
            red[lr * 4 + nw]       = m[i][0];
            red[(lr + 8) * 4 + nw] = m[i][1];
        }
    }
    __syncthreads();
    float rm[4][2];
#pragma unroll
    for (int i = 0; i < 4; i++) {
        const int lr = mw * 64 + i * 16 + r4;
        rm[i][0] = fmaxf(fmaxf(red[lr * 4], red[lr * 4 + 1]),
                         fmaxf(red[lr * 4 + 2], red[lr * 4 + 3]));
        rm[i][1] = fmaxf(fmaxf(red[(lr + 8) * 4], red[(lr + 8) * 4 + 1]),
                         fmaxf(red[(lr + 8) * 4 + 2], red[(lr + 8) * 4 + 3]));
    }
    __syncthreads();

    float sme[4][2];
#pragma unroll
    for (int i = 0; i < 4; i++) {
        float s0 = 0.f, s1 = 0.f;
#pragma unroll
        for (int j = 0; j < 8; j++) {
            s0 += __expf(acc[i][j][0] - rm[i][0]) + __expf(acc[i][j][1] - rm[i][0]);
            s1 += __expf(acc[i][j][2] - rm[i][1]) + __expf(acc[i][j][3] - rm[i][1]);
        }
        s0 += __shfl_xor_sync(0xffffffffu, s0, 1);
        s0 += __shfl_xor_sync(0xffffffffu, s0, 2);
        s1 += __shfl_xor_sync(0xffffffffu, s1, 1);
        s1 += __shfl_xor_sync(0xffffffffu, s1, 2);
        sme[i][0] = s0; sme[i][1] = s1;
    }
    if ((lane & 3) == 0) {
#pragma unroll
        for (int i = 0; i < 4; i++) {
            const int lr = mw * 64 + i * 16 + r4;
            red[lr * 4 + nw]       = sme[i][0];
            red[(lr + 8) * 4 + nw] = sme[i][1];
        }
    }
    __syncthreads();

#pragma unroll
    for (int i = 0; i < 4; i++) {
        const int lr = mw * 64 + i * 16 + r4;
        const float ls0 = __logf(red[lr * 4] + red[lr * 4 + 1]
                               + red[lr * 4 + 2] + red[lr * 4 + 3]);
        const float ls1 = __logf(red[(lr + 8) * 4] + red[(lr + 8) * 4 + 1]
                               + red[(lr + 8) * 4 + 2] + red[(lr + 8) * 4 + 3]);
        const int row0 = m0 + lr;
        float* o0 = out + ((long long)b * kU + row0) * kT;
        float* o1 = o0 + 8LL * kT;
#pragma unroll
        for (int j = 0; j < 8; j++) {
            const int col = nw * 64 + j * 8 + c2;
            store_pair(o0 + col, acc[i][j][0] - rm[i][0] - ls0,
                                 acc[i][j][1] - rm[i][0] - ls0);
            store_pair(o1 + col, acc[i][j][2] - rm[i][1] - ls1,
                                 acc[i][j][3] - rm[i][1] - ls1);
        }
    }
}

// ---------------------------------------------------------------------------
// Fused flash attention (exact R10 version — measured best).
// ---------------------------------------------------------------------------
__global__ void __launch_bounds__(256, 1)
flash_attn(const __nv_bfloat16* __restrict__ qkv, __nv_bfloat16* __restrict__ att,
           const int* __restrict__ pad, int S)
{
    constexpr int RSB = 272;
    constexpr int OFF_Q = 4096;
    constexpr int TILE = 128 * RSB;
    constexpr int OFF_S = OFF_Q + TILE;
    constexpr int STAGE = 2 * TILE;

    extern __shared__ char sm[];
    int* spad = (int*)sm;
    const uint32_t sb = smem_u32(sm);

    const int bh = blockIdx.y;
    const int b = bh >> 3, h = bh & 7;
    const int q0 = blockIdx.x * 128;
    const int tid = threadIdx.x;
    const int lane = tid & 31;
    const int w = tid >> 5;

    for (int i = tid; i < S; i += 256) spad[i] = pad[b * S + i];

    {
        const __nv_bfloat16* qg = qkv + ((long long)b * S + q0) * 3072 + h * 128;
#pragma unroll
        for (int i = 0; i < 8; i++) {
            const int c = tid + i * 256;
            const int r = c >> 4, cc = c & 15;
            cp_async16(sb + OFF_Q + r * RSB + cc * 16, qg + (long long)r * 3072 + cc * 8);
        }
        CP_COMMIT();
    }

    auto load_kv = [&](int t) {
        const uint32_t s = sb + OFF_S + (t & 1) * STAGE;
        const __nv_bfloat16* kg = qkv + ((long long)b * S + t * 128) * 3072 + 1024 + h * 128;
#pragma unroll
        for (int i = 0; i < 16; i++) {
            const int c = tid + i * 256;
            const int r = (c >> 4) & 127, cc = c & 15;
            const int kv = c >> 11;
            cp_async16(s + kv * TILE + r * RSB + cc * 16,
                       kg + (long long)r * 3072 + kv * 1024 + cc * 8);
        }
        CP_COMMIT();
    };

    load_kv(0);
    CP_WAIT(1);
    __syncthreads();

    uint32_t qa[8][4];
#pragma unroll
    for (int kb = 0; kb < 8; kb++) {
        const int row = w * 16 + (lane & 15);
        ldmx4(qa[kb], sb + OFF_Q + row * RSB + (kb * 2 + (lane >> 4)) * 16);
    }

    float o[16][4] = {};
    float m0 = -CUDART_INF_F, m1 = -CUDART_INF_F;
    float l0 = 0.f, l1 = 0.f;
    const int c2 = (lane & 3) * 2;

    const int nt = S >> 7;
    for (int t = 0; t < nt; t++) {
        if (t + 1 < nt) { load_kv(t + 1); CP_WAIT(1); } else { CP_WAIT(0); }
        __syncthreads();
        const uint32_t sK = sb + OFF_S + (t & 1) * STAGE;
        const uint32_t sV = sK + TILE;

        float s[16][4] = {};
#pragma unroll
        for (int kb = 0; kb < 8; kb++) {
#pragma unroll
            for (int jj = 0; jj < 8; jj++) {
                uint32_t kf[4];
                const int row = jj * 16 + (lane & 7) + ((lane >> 4) << 3);
                ldmx4(kf, sK + row * RSB + (kb * 2 + ((lane >> 3) & 1)) * 16);
                mma_bf16(s[jj * 2], qa[kb], &kf[0]);
                mma_bf16(s[jj * 2 + 1], qa[kb], &kf[2]);
            }
        }

        float mt0 = -CUDART_INF_F, mt1 = -CUDART_INF_F;
#pragma unroll
        for (int j = 0; j < 16; j++) {
            const int col = t * 128 + j * 8 + c2;
            const bool p0 = spad[col] != 0, p1 = spad[col + 1] != 0;
            s[j][0] = p0 ? kNeg : s[j][0] * kScale;
            s[j][1] = p1 ? kNeg : s[j][1] * kScale;
            s[j][2] = p0 ? kNeg : s[j][2] * kScale;
            s[j][3] = p1 ? kNeg : s[j][3] * kScale;
            mt0 = fmaxf(mt0, fmaxf(s[j][0], s[j][1]));
            mt1 = fmaxf(mt1, fmaxf(s[j][2], s[j][3]));
        }
        mt0 = fmaxf(mt0, __shfl_xor_sync(0xffffffffu, mt0, 1));
        mt0 = fmaxf(mt0, __shfl_xor_sync(0xffffffffu, mt0, 2));
        mt1 = fmaxf(mt1, __shfl_xor_sync(0xffffffffu, mt1, 1));
        mt1 = fmaxf(mt1, __shfl_xor_sync(0xffffffffu, mt1, 2));

        const float mn0 = fmaxf(m0, mt0), mn1 = fmaxf(m1, mt1);
        const float a0 = __expf(m0 - mn0), a1 = __expf(m1 - mn1);
        m0 = mn0; m1 = mn1;

        float t0 = 0.f, t1 = 0.f;
#pragma unroll
        for (int j = 0; j < 16; j++) {
            s[j][0] = __expf(s[j][0] - mn0);
            s[j][1] = __expf(s[j][1] - mn0);
            s[j][2] = __expf(s[j][2] - mn1);
            s[j][3] = __expf(s[j][3] - mn1);
            t0 += s[j][0] + s[j][1];
            t1 += s[j][2] + s[j][3];
        }
        t0 += __shfl_xor_sync(0xffffffffu, t0, 1);
        t0 += __shfl_xor_sync(0xffffffffu, t0, 2);
        t1 += __shfl_xor_sync(0xffffffffu, t1, 1);
        t1 += __shfl_xor_sync(0xffffffffu, t1, 2);
        l0 = l0 * a0 + t0;
        l1 = l1 * a1 + t1;
#pragma unroll
        for (int j = 0; j < 16; j++) {
            o[j][0] *= a0; o[j][1] *= a0;
            o[j][2] *= a1; o[j][3] *= a1;
        }

#pragma unroll
        for (int kb = 0; kb < 8; kb++) {
            uint32_t pa[4];
            pa[0] = packbf(s[kb * 2][0], s[kb * 2][1]);
            pa[1] = packbf(s[kb * 2][2], s[kb * 2][3]);
            pa[2] = packbf(s[kb * 2 + 1][0], s[kb * 2 + 1][1]);
            pa[3] = packbf(s[kb * 2 + 1][2], s[kb * 2 + 1][3]);
#pragma unroll
            for (int jj = 0; jj < 8; jj++) {
                uint32_t vf[4];
                const int row = kb * 16 + (lane & 7) + (((lane >> 3) & 1) << 3);
                ldmx4t(vf, sV + row * RSB + (jj * 2 + (lane >> 4)) * 16);
                mma_bf16(o[jj * 2], pa, &vf[0]);
                mma_bf16(o[jj * 2 + 1], pa, &vf[2]);
            }
        }
        __syncthreads();
    }

    const float inv0 = 1.f / l0, inv1 = 1.f / l1;
    const int row0 = q0 + w * 16 + (lane >> 2);
    __nv_bfloat16* op0 = att + ((long long)b * S + row0) * 1024 + h * 128;
    __nv_bfloat16* op1 = op0 + 8LL * 1024;
#pragma unroll
    for (int j = 0; j < 16; j++) {
        const int col = j * 8 + c2;
        store_pair(op0 + col, o[j][0] * inv0, o[j][1] * inv0);
        store_pair(op1 + col, o[j][2] * inv1, o[j][3] * inv1);
    }
}

// ---------------------------------------------------------------------------
// Weight conversions: fp32->bf16 (2 segments) and fp32->fp8 e4m3 x16 (2 segs)
// ---------------------------------------------------------------------------
__global__ void f2bf2_kernel(const float* s0, __nv_bfloat16* d0, long long n0,
                             const float* s1, __nv_bfloat16* d1, long long n1)
{
    const int seg = blockIdx.y;
    const float* src = seg ? s1 : s0;
    __nv_bfloat16* dst = seg ? d1 : d0;
    const long long n = seg ? n1 : n0;
    const long long i = ((long long)blockIdx.x * 256 + threadIdx.x) * 4;
    if (i >= n) return;
    const float4 v = *(const float4*)(src + i);
    *(__nv_bfloat162*)(dst + i)     = __floats2bfloat162_rn(v.x, v.y);
    *(__nv_bfloat162*)(dst + i + 2) = __floats2bfloat162_rn(v.z, v.w);
}

__global__ void f2f8_kernel(const float* s0, uint8_t* d0, long long n0,
                            const float* s1, uint8_t* d1, long long n1)
{
    const int seg = blockIdx.y;
    const float* src = seg ? s1 : s0;
    uint8_t* dst = seg ? d1 : d0;
    const long long n = seg ? n1 : n0;
    const long long i = ((long long)blockIdx.x * 256 + threadIdx.x) * 4;
    if (i >= n) return;
    const float4 v = *(const float4*)(src + i);
    const uint16_t lo = packf8(v.x * kWScale, v.y * kWScale);
    const uint16_t hi = packf8(v.z * kWScale, v.w * kWScale);
    *(uint32_t*)(dst + i) = (uint32_t)lo | ((uint32_t)hi << 16);
}

// ---------------------------------------------------------------------------
// Embedding gather (fp32 table -> bf16) + pad flags
// ---------------------------------------------------------------------------
__global__ void embed_kernel(const int* __restrict__ tok, const float* __restrict__ emb,
                             __nv_bfloat16* __restrict__ x, int* __restrict__ pad, int padidx)
{
    const int n = blockIdx.x;
    const int t = tok[n];
    if (threadIdx.x == 0) pad[n] = (t == padidx) ? 1 : 0;
    const float4* src = (const float4*)(emb + (size_t)t * kD);
    __nv_bfloat162* dst = (__nv_bfloat162*)(x + (size_t)n * kD);
    for (int i = threadIdx.x; i < kD / 4; i += blockDim.x) {
        const float4 v = src[i];
        dst[i * 2]     = __floats2bfloat162_rn(v.x, v.y);
        dst[i * 2 + 1] = __floats2bfloat162_rn(v.z, v.w);
    }
}

// ---------------------------------------------------------------------------
// Reduction helpers (blockDim.x == 256)
// ---------------------------------------------------------------------------
__device__ __forceinline__ float warp_sum(float v) {
#pragma unroll
    for (int o = 16; o > 0; o >>= 1) v += __shfl_xor_sync(0xffffffffu, v, o);
    return v;
}
__device__ __forceinline__ float block_sum(float v, float* sh) {
    v = warp_sum(v);
    if ((threadIdx.x & 31) == 0) sh[threadIdx.x >> 5] = v;
    __syncthreads();
    float r = 0.f;
#pragma unroll
    for (int i = 0; i < 8; i++) r += sh[i];
    __syncthreads();
    return r;
}

// ---------------------------------------------------------------------------
// x = LayerNorm(x + y); optional |x|^2 per row (nrm) and fp8 copy (x8).
// ---------------------------------------------------------------------------
__global__ void add_ln_kernel(__nv_bfloat16* __restrict__ x,
                              const __nv_bfloat16* __restrict__ y,
                              const float* __restrict__ gamma,
                              const float* __restrict__ beta,
                              float* __restrict__ nrm,
                              uint8_t* __restrict__ x8)
{
    __shared__ float sh[8];
    const long long row = blockIdx.x;
    __nv_bfloat16* xp = x + row * kD;
    const __nv_bfloat16* yp = y + row * kD;

    float v[4];
    float s = 0.f;
#pragma unroll
    for (int i = 0; i < 4; i++) {
        const int idx = threadIdx.x + (i << 8);
        v[i] = __bfloat162float(xp[idx]) + __bfloat162float(yp[idx]);
        s += v[i];
    }
    s = block_sum(s, sh);
    const float mean = s * (1.f / kD);
    float sq = 0.f;
#pragma unroll
    for (int i = 0; i < 4; i++) { const float d = v[i] - mean; sq += d * d; }
    sq = block_sum(sq, sh);
    const float r = rsqrtf(sq * (1.f / kD) + kLnEps);
    float nsq = 0.f;
#pragma unroll
    for (int i = 0; i < 4; i++) {
        const int idx = threadIdx.x + (i << 8);
        const float fv = (v[i] - mean) * r * gamma[idx] + beta[idx];
        xp[idx] = __float2bfloat16_rn(fv);
        if (x8) x8[row * kD + idx] = (uint8_t)packf8(fv, 0.f);
        if (nrm) { const float q = __bfloat162float(xp[idx]); nsq += q * q; }
    }
    if (nrm) {
        nsq = block_sum(nsq, sh);
        if (threadIdx.x == 0) nrm[row] = nsq;
    }
}

// ---------------------------------------------------------------------------
// Host orchestration
// ---------------------------------------------------------------------------
namespace {

constexpr size_t kGemmSmem  = 3 * 256 * 144;                              // 110592
constexpr size_t kFlashSmem = 4096 + 128 * 272 + 2 * (2 * 128 * 272);     // 178176
constexpr size_t kCrossSmem = 3 * 384 * 144;                              // 165888

struct EncParams {
    const float *emb, *ipb, *ob, *l1s, *l1b, *f1b, *f2b, *l2s, *l2b;
    const __nv_bfloat16 *ipw, *ow;
    const uint8_t *f1w8, *f2w8;
};

void run_encoder(cudaStream_t st, const int* tokens, int Slen, int padidx,
                 const EncParams& P, __nv_bfloat16* x, uint8_t* x8, int* pad,
                 __nv_bfloat16* qkv, __nv_bfloat16* att, __nv_bfloat16* tmp,
                 uint8_t* f8b, float* norm)
{
    const int Ntok = kB * Slen;
    embed_kernel<<<Ntok, 256, 0, st>>>(tokens, P.emb, x, pad, padidx);

    for (int l = 0; l < kL; l++) {
        const __nv_bfloat16* ipw = P.ipw + (long long)l * 3 * kD * kD;
        const __nv_bfloat16* ow  = P.ow  + (long long)l * kD * kD;
        const uint8_t* f1w8 = P.f1w8 + (long long)l * kFF * kD;
        const uint8_t* f2w8 = P.f2w8 + (long long)l * kD * kFF;
        const float* ipb = P.ipb + (size_t)l * 3 * kD;
        const float* ob  = P.ob  + (size_t)l * kD;
        const float* l1s = P.l1s + (size_t)l * kD;
        const float* l1b = P.l1b + (size_t)l * kD;
        const float* f1b = P.f1b + (size_t)l * kFF;
        const float* f2b = P.f2b + (size_t)l * kD;
        const float* l2s = P.l2s + (size_t)l * kD;
        const float* l2b = P.l2b + (size_t)l * kD;

        bf_gemm<__nv_bfloat16, false><<<dim3(3 * kD / 128, Ntok / 128, 1), 128, kGemmSmem, st>>>(
            x, ipw, ipb, qkv, kD, kD, kD, 3 * kD, 1, 0, 0, 0, 0, 0, 0);

        flash_attn<<<dim3(Slen / 128, kB * kH), 256, kFlashSmem, st>>>(qkv, att, pad, Slen);

        bf_gemm<__nv_bfloat16, false><<<dim3(kD / 128, Ntok / 128, 1), 128, kGemmSmem, st>>>(
            att, ow, ob, tmp, kD, kD, kD, kD, 1, 0, 0, 0, 0, 0, 0);

        // LN1 also emits fp8 activations for the fp8 FFN
        add_ln_kernel<<<Ntok, 256, 0, st>>>(x, tmp, l1s, l1b, nullptr, x8);

        // FFN in fp8 (weights pre-scaled x16; epilogue undoes it)
        f8_gemm<uint8_t, true><<<dim3(kFF / 128, Ntok / 128, 1), 128, kGemmSmem, st>>>(
            x8, f1w8, f1b, f8b, kD, kD, kD, kFF, kWInv);

        f8_gemm<__nv_bfloat16, false><<<dim3(kD / 128, Ntok / 128, 1), 128, kGemmSmem, st>>>(
            f8b, f2w8, f2b, tmp, kFF, kFF, kFF, kD, kWInv);

        add_ln_kernel<<<Ntok, 256, 0, st>>>(x, tmp, l2s, l2b,
                                            l == kL - 1 ? norm : nullptr, nullptr);
    }
}

}  // namespace

extern "C" void kernel_launch(void* const* d_in, const int* in_sizes, int n_in,
                              void* d_out, int out_size)
{
    (void)in_sizes; (void)n_in; (void)out_size;
    const int* text_tokens = (const int*)d_in[0];
    const int* unit_tokens = (const int*)d_in[1];
    auto f = [&](int i) { return (const float*)d_in[i]; };
    float* out = (float*)d_out;

    cudaFuncSetAttribute(bf_gemm<__nv_bfloat16, false>,
                         cudaFuncAttributeMaxDynamicSharedMemorySize, (int)kGemmSmem);
    cudaFuncSetAttribute(f8_gemm<uint8_t, true>,
                         cudaFuncAttributeMaxDynamicSharedMemorySize, (int)kGemmSmem);
    cudaFuncSetAttribute(f8_gemm<__nv_bfloat16, false>,
                         cudaFuncAttributeMaxDynamicSharedMemorySize, (int)kGemmSmem);
    cudaFuncSetAttribute(flash_attn,
                         cudaFuncAttributeMaxDynamicSharedMemorySize, (int)kFlashSmem);
    cudaFuncSetAttribute(cross_dist_kernel,
                         cudaFuncAttributeMaxDynamicSharedMemorySize, (int)kCrossSmem);

    __nv_bfloat16 *x_u, *x_t, *qkv_u, *att_u, *tmp_u;
    __nv_bfloat16 *qkv_t, *att_t, *tmp_t, *wbf;
    uint8_t *x8_u, *x8_t, *f8b_u, *f8b_t, *w8;
    float *un, *tn;
    int *pad_u, *pad_t;
    cudaGetSymbolAddress((void**)&x_u, g_x_u);
    cudaGetSymbolAddress((void**)&x_t, g_x_t);
    cudaGetSymbolAddress((void**)&x8_u, g_x8_u);
    cudaGetSymbolAddress((void**)&x8_t, g_x8_t);
    cudaGetSymbolAddress((void**)&qkv_u, g_qkv_u);
    cudaGetSymbolAddress((void**)&att_u, g_att_u);
    cudaGetSymbolAddress((void**)&tmp_u, g_tmp_u);
    cudaGetSymbolAddress((void**)&f8b_u, g_f8b_u);
    cudaGetSymbolAddress((void**)&qkv_t, g_qkv_t);
    cudaGetSymbolAddress((void**)&att_t, g_att_t);
    cudaGetSymbolAddress((void**)&tmp_t, g_tmp_t);
    cudaGetSymbolAddress((void**)&f8b_t, g_f8b_t);
    cudaGetSymbolAddress((void**)&wbf, g_wbf);
    cudaGetSymbolAddress((void**)&w8, g_w8);
    cudaGetSymbolAddress((void**)&un, g_un);
    cudaGetSymbolAddress((void**)&tn, g_tn);
    cudaGetSymbolAddress((void**)&pad_u, g_pad_u);
    cudaGetSymbolAddress((void**)&pad_t, g_pad_t);

    EncParams tP, uP;
    {
        const __nv_bfloat16* w = wbf;
        const uint8_t* w8p = w8;
        tP = EncParams{f(2), f(4), f(6), f(7), f(8), f(10), f(12), f(13), f(14),
                       w, w + kWipw, w8p, w8p + kWf1};
        const __nv_bfloat16* w2 = wbf + kWEnc;
        const uint8_t* w8p2 = w8 + kW8Enc;
        uP = EncParams{f(15), f(17), f(19), f(20), f(21), f(23), f(25), f(26), f(27),
                       w2, w2 + kWipw, w8p2, w8p2 + kWf1};
    }

    // --- fork ONE side stream (proven compliant footprint) ---
    cudaStream_t s1;
    cudaStreamCreateWithFlags(&s1, cudaStreamNonBlocking);
    cudaEvent_t eFork, eJoin;
    cudaEventCreateWithFlags(&eFork, cudaEventDisableTiming);
    cudaEventCreateWithFlags(&eJoin, cudaEventDisableTiming);

    cudaEventRecord(eFork, 0);
    cudaStreamWaitEvent(s1, eFork, 0);

    // s1: text weight conversions + full text pipeline
    f2bf2_kernel<<<dim3((int)(kWipw / 1024), 2), 256, 0, s1>>>(
        f(3), wbf, kWipw, f(5), wbf + kWipw, kWow);
    f2f8_kernel<<<dim3((int)(kWf1 / 1024), 2), 256, 0, s1>>>(
        f(9), w8, kWf1, f(11), w8 + kWf1, kWf2);
    run_encoder(s1, text_tokens, kT, kTextV - 1, tP, x_t, x8_t, pad_t,
                qkv_t, att_t, tmp_t, f8b_t, tn);
    cudaEventRecord(eJoin, s1);

    // main: unit weight conversions + unit pipeline
    f2bf2_kernel<<<dim3((int)(kWipw / 1024), 2), 256>>>(
        f(16), wbf + kWEnc, kWipw, f(18), wbf + kWEnc + kWipw, kWow);
    f2f8_kernel<<<dim3((int)(kWf1 / 1024), 2), 256>>>(
        f(22), w8 + kW8Enc, kWf1, f(24), w8 + kW8Enc + kWf1, kWf2);
    run_encoder(0, unit_tokens, kU, kUnitV - 1, uP, x_u, x8_u, pad_u,
                qkv_u, att_u, tmp_u, f8b_u, un);

    // join, then fused cross + dist + log-softmax
    cudaStreamWaitEvent(0, eJoin, 0);
    cross_dist_kernel<<<dim3(kU / 128, kB), 256, kCrossSmem>>>(
        x_u, x_t, un, tn, pad_u, pad_t, out);
}